// round 1
// baseline (speedup 1.0000x reference)
#include <cuda_runtime.h>
#include <math.h>

// Problem constants (GlobalLocalAttention_74887049773165): b=2, nc=64, H=W=64
#define Bz 2
#define NC 64
#define Hh 64
#define Ww 64
#define Ls 4096          // H*W
#define KD 576           // nc * 3 * 3
#define EPSF 1e-7f

// Scratch (worst-case cnt == Ls; actual data gives cnt ~ 8 per sample)
__device__ int   g_cnt[Bz];
__device__ int   g_list[Bz][Ls];
__device__ float g_K[Bz][Ls][KD];     // normalized bg patch rows (candidates only)
__device__ float g_corr[Bz][Ls][Ls];  // corr rows    (candidates only)
__device__ float g_sc[Bz][Ls][Ls];    // score rows   (candidates only)

// ---------------------------------------------------------------------------
// K1: per-sample, one block: compute mm[l] and compact candidate l's IN INDEX
// ORDER (deterministic; preserves jnp.argmax first-occurrence tie-break).
// ---------------------------------------------------------------------------
__global__ void k_scan(const float* __restrict__ mask) {
    int b = blockIdx.x;
    const float* m = mask + b * Ls;
    __shared__ int wcnt[8];
    __shared__ int scnt;
    int tid = threadIdx.x, lane = tid & 31, warp = tid >> 5;
    if (tid == 0) scnt = 0;
    __syncthreads();
    for (int base = 0; base < Ls; base += 256) {
        int l = base + tid;
        int y = l >> 6, x = l & 63;
        int ok = 1;
        #pragma unroll
        for (int dy = -1; dy <= 1; dy++) {
            int yy = y + dy;
            if (yy < 0 || yy >= Hh) continue;
            #pragma unroll
            for (int dx = -1; dx <= 1; dx++) {
                int xx = x + dx;
                if (xx >= 0 && xx < Ww && m[yy * Ww + xx] != 0.0f) ok = 0;
            }
        }
        unsigned wm = __ballot_sync(0xffffffffu, ok);
        if (lane == 0) wcnt[warp] = __popc(wm);
        __syncthreads();
        int off = scnt;
        for (int w = 0; w < warp; w++) off += wcnt[w];
        if (ok) g_list[b][off + __popc(wm & ((1u << lane) - 1u))] = l;
        __syncthreads();
        if (tid == 0) {
            int t = 0;
            for (int w = 0; w < 8; w++) t += wcnt[w];
            scnt += t;
        }
        __syncthreads();
    }
    if (tid == 0) g_cnt[b] = scnt;
}

// ---------------------------------------------------------------------------
// K2: build normalized kernel rows for candidates.
// K[l][c*9+ph*3+pw] = (bg_pad + EPS) / ||patch + EPS||, bg = background*(1-mask)
// ---------------------------------------------------------------------------
__global__ void k_build(const float* __restrict__ bgin, const float* __restrict__ mask) {
    int b = blockIdx.y;
    int cnt = g_cnt[b];
    int tid = threadIdx.x;
    __shared__ float sval[KD];
    __shared__ float ssum[256];
    for (int i = blockIdx.x; i < cnt; i += gridDim.x) {
        int l = g_list[b][i];
        int y = l >> 6, x = l & 63;
        float acc = 0.f;
        for (int k = tid; k < KD; k += 256) {
            int c = k / 9, pp = k % 9;
            int ph = pp / 3, pw = pp % 3;
            int yy = y + ph - 1, xx = x + pw - 1;
            float v = 0.f;
            if (yy >= 0 && yy < Hh && xx >= 0 && xx < Ww) {
                float mv = mask[b * Ls + yy * Ww + xx];
                v = bgin[(b * NC + c) * Ls + yy * Ww + xx] * (1.f - mv);
            }
            v += EPSF;
            sval[k] = v;
            acc += v * v;
        }
        ssum[tid] = acc;
        __syncthreads();
        for (int off = 128; off > 0; off >>= 1) {
            if (tid < off) ssum[tid] += ssum[tid + off];
            __syncthreads();
        }
        float norm = sqrtf(ssum[0]);
        for (int k = tid; k < KD; k += 256) g_K[b][i][k] = sval[k] / norm;
        __syncthreads();
    }
}

// ---------------------------------------------------------------------------
// K3: corr[i][s] = <K_i, fg patch at s> (zero-padded fg)
// ---------------------------------------------------------------------------
__global__ void k_corr(const float* __restrict__ fgin) {
    int b = blockIdx.z;
    int cnt = g_cnt[b];
    int tid = threadIdx.x;
    int s = blockIdx.x * 256 + tid;
    int y = s >> 6, x = s & 63;
    const float* fg = fgin + b * NC * Ls;
    __shared__ float sk[KD];
    for (int i = blockIdx.y; i < cnt; i += gridDim.y) {
        for (int k = tid; k < KD; k += 256) sk[k] = g_K[b][i][k];
        __syncthreads();
        float acc = 0.f;
        for (int c = 0; c < NC; c++) {
            const float* fc = fg + c * Ls;
            const float* kc = sk + c * 9;
            #pragma unroll
            for (int ph = 0; ph < 3; ph++) {
                int yy = y + ph - 1;
                if (yy < 0 || yy >= Hh) continue;
                const float* fr = fc + yy * Ww;
                #pragma unroll
                for (int pw = 0; pw < 3; pw++) {
                    int xx = x + pw - 1;
                    if (xx >= 0 && xx < Ww) acc += kc[ph * 3 + pw] * fr[xx];
                }
            }
        }
        g_corr[b][i][s] = acc;
        __syncthreads();
    }
}

// 3x3 spatial box-sum of a corr row (zero outside grid)
__device__ __forceinline__ float boxsum(const float* __restrict__ row, int y, int x) {
    float a = 0.f;
    #pragma unroll
    for (int dy = -1; dy <= 1; dy++) {
        int yy = y + dy;
        if (yy < 0 || yy >= Hh) continue;
        const float* r = row + yy * Ww;
        #pragma unroll
        for (int dx = -1; dx <= 1; dx++) {
            int xx = x + dx;
            if (xx >= 0 && xx < Ww) a += r[xx];
        }
    }
    return a;
}

// ---------------------------------------------------------------------------
// K4: per spatial s: v_i = 10 * boxsum(corr_i); softmax over the full l-axis
// where masked rows contribute exp(0 - vmax) each (closed form); scores for
// candidates; argmax -> flow.
// ---------------------------------------------------------------------------
__global__ void k_soft(float* __restrict__ flowout) {
    int b = blockIdx.y;
    int cnt = g_cnt[b];
    int tid = threadIdx.x;
    int s = blockIdx.x * 256 + tid;
    int y = s >> 6, x = s & 63;

    float vmax = (cnt < Ls) ? 0.f : -INFINITY;
    for (int i = 0; i < cnt; i++) {
        float v = 10.f * boxsum(&g_corr[b][i][0], y, x);
        vmax = fmaxf(vmax, v);
    }
    float denom = (cnt < Ls) ? (float)(Ls - cnt) * expf(-vmax) : 0.f;
    float bestv = -INFINITY;
    int bestl = 0x7fffffff;
    for (int i = 0; i < cnt; i++) {
        float v = 10.f * boxsum(&g_corr[b][i][0], y, x);
        float e = expf(v - vmax);
        denom += e;
        int l = g_list[b][i];
        if (v > bestv || (v == bestv && l < bestl)) { bestv = v; bestl = l; }
        g_sc[b][i][s] = e;
    }
    float inv = 1.f / denom;
    for (int i = 0; i < cnt; i++) g_sc[b][i][s] *= inv;

    int lb = (cnt > 0) ? bestl : 0;
    flowout[(b * 2 + 0) * Ls + s] = (float)(lb >> 6) - (float)y;
    flowout[(b * 2 + 1) * Ls + s] = (float)(lb & 63) - (float)x;
}

// ---------------------------------------------------------------------------
// K5: rec[c,y,x] = sum_{ph,pw} sum_i scores[i, (y+1-ph, x+1-pw)] * K[i, c*9+pp]
// final = (rec*m/9)*m + fg*(1-m)
// ---------------------------------------------------------------------------
__global__ void k_rec(const float* __restrict__ fgin, const float* __restrict__ mask,
                      float* __restrict__ att) {
    int b = blockIdx.y;
    int cnt = g_cnt[b];
    int tid = threadIdx.x;
    int s = blockIdx.x * 4 + (tid >> 6);
    int c = tid & 63;
    int y = s >> 6, x = s & 63;
    float acc = 0.f;
    #pragma unroll
    for (int ph = 0; ph < 3; ph++) {
        int yy = y + 1 - ph;
        if (yy < 0 || yy >= Hh) continue;
        #pragma unroll
        for (int pw = 0; pw < 3; pw++) {
            int xx = x + 1 - pw;
            if (xx < 0 || xx >= Ww) continue;
            int s2 = yy * Ww + xx;
            int kk = c * 9 + ph * 3 + pw;
            for (int i = 0; i < cnt; i++)
                acc += g_sc[b][i][s2] * g_K[b][i][kk];
        }
    }
    float mv = mask[b * Ls + s];
    float fgv = fgin[(b * NC + c) * Ls + s];
    float rec = (acc * mv) / 9.f;
    att[(b * NC + c) * Ls + s] = rec * mv + fgv * (1.f - mv);
}

// ---------------------------------------------------------------------------
extern "C" void kernel_launch(void* const* d_in, const int* in_sizes, int n_in,
                              void* d_out, int out_size) {
    const float* fg   = (const float*)d_in[0];   // foreground [2,64,64,64]
    const float* bg   = (const float*)d_in[1];   // background [2,64,64,64]
    const float* mask = (const float*)d_in[2];   // mask       [2,1,64,64]
    float* att  = (float*)d_out;                 // attended   [2,64,64,64]
    float* flow = (float*)d_out + Bz * NC * Ls;  // flow       [2,2,64,64]

    k_scan<<<Bz, 256>>>(mask);
    k_build<<<dim3(64, Bz), 256>>>(bg, mask);
    k_corr<<<dim3(16, 64, Bz), 256>>>(fg);
    k_soft<<<dim3(16, Bz), 256>>>(flow);
    k_rec<<<dim3(1024, Bz), 256>>>(fg, mask, att);
}